// round 1
// baseline (speedup 1.0000x reference)
#include <cuda_runtime.h>
#include <cuda_bf16.h>

// Problem constants
#define BB 8
#define NPTS 16384
#define NG 512          // NUM_GROUPS
#define GS 32           // GROUP_SIZE
#define UK 512          // UPSCALE_K
#define CTX 256         // CONTEXT
#define R2 0.25f        // RADIUS^2

// Output layout (float32, flattened concat of the reference tuple)
#define OFF_GROUPS   0          // 8*256*32*4 = 262144
#define OFF_CENTERS  262144     // 8*256*4   = 8192
#define OFF_EMASK    270336     // 8*256     = 2048
#define OFF_PMASK    272384     // 8*256*32  = 65536
// total 337920

// ---------------- device scratch (no allocations allowed) ----------------
__device__ float4             g_centers[BB * NG];                 // FPS centers (x,y,z,energy)
__device__ unsigned long long g_cand[(size_t)BB * NG * UK];       // 16MB candidate keys
__device__ int                g_cand_cnt[BB * NG];
__device__ int                g_group_len[BB];

// exact (no fma contraction) squared distance, reduce order ((dx^2+dy^2)+dz^2)
__device__ __forceinline__ float d2_exact(float dx, float dy, float dz) {
    return __fadd_rn(__fadd_rn(__fmul_rn(dx, dx), __fmul_rn(dy, dy)), __fmul_rn(dz, dz));
}

// =====================================================================
// K1: Farthest point sampling. 1 CTA per batch, 512 threads, 32 pts/thread
// held in registers. Winner's xyz is carried through the reductions.
// =====================================================================
#define FPS_T 512
#define SLOTS 32

__global__ __launch_bounds__(FPS_T, 1)
void fps_kernel(const float4* __restrict__ pts, const int* __restrict__ lengths,
                float* __restrict__ out_centers /* d_out + OFF_CENTERS */) {
    const int b = blockIdx.x;
    const int t = threadIdx.x;
    const float4* __restrict__ P = pts + (size_t)b * NPTS;
    const int len = lengths[b];

    __shared__ float s_lx, s_ly, s_lz;
    __shared__ float s_rv[16], s_rx[16], s_ry[16], s_rz[16];
    __shared__ int   s_rp[16];
    __shared__ int   s_cidx[NG];

    float x[SLOTS], y[SLOTS], z[SLOTS], mind[SLOTS];
    const float INF = __int_as_float(0x7f800000);

#pragma unroll
    for (int i = 0; i < SLOTS; i++) {
        int p = i * FPS_T + t;
        float4 v = P[p];
        bool valid = (p < len);
        x[i] = valid ? v.x : INF;
        y[i] = valid ? v.y : INF;
        z[i] = valid ? v.z : INF;
        mind[i] = valid ? 1e10f : -1e30f;   // invalid points can never win argmax
    }
    if (t == 0) {
        float4 v0 = P[0];
        s_lx = v0.x; s_ly = v0.y; s_lz = v0.z;
        s_cidx[0] = 0;
        g_group_len[b] = 0;
    }
    __syncthreads();

    const int wid = t >> 5, lane = t & 31;

    for (int k = 1; k < NG; k++) {
        const float lx = s_lx, ly = s_ly, lz = s_lz;

        // pass 1: update mind, find max value
        float fm = -1e38f;
#pragma unroll
        for (int i = 0; i < SLOTS; i++) {
            float dx = x[i] - lx, dy = y[i] - ly, dz = z[i] - lz;
            float d2 = d2_exact(dx, dy, dz);
            mind[i] = fminf(mind[i], d2);
            fm = fmaxf(fm, mind[i]);
        }
        // pass 2 (reverse: last write = smallest slot index = smallest point idx)
        float bv = fm, bx = 0.f, by = 0.f, bz = 0.f;
        int bp = 0x7FFFFFFF;
#pragma unroll
        for (int i = SLOTS - 1; i >= 0; i--) {
            if (mind[i] == fm) { bp = i * FPS_T + t; bx = x[i]; by = y[i]; bz = z[i]; }
        }

        // warp argmax (value desc, index asc on ties), xyz carried
#pragma unroll
        for (int o = 16; o > 0; o >>= 1) {
            float ov = __shfl_down_sync(0xffffffffu, bv, o);
            int   op = __shfl_down_sync(0xffffffffu, bp, o);
            float ox = __shfl_down_sync(0xffffffffu, bx, o);
            float oy = __shfl_down_sync(0xffffffffu, by, o);
            float oz = __shfl_down_sync(0xffffffffu, bz, o);
            bool take = (ov > bv) || (ov == bv && op < bp);
            if (take) { bv = ov; bp = op; bx = ox; by = oy; bz = oz; }
        }
        if (lane == 0) { s_rv[wid] = bv; s_rp[wid] = bp; s_rx[wid] = bx; s_ry[wid] = by; s_rz[wid] = bz; }
        __syncthreads();

        if (t < 32) {
            bool have = (t < 16);
            float v2 = have ? s_rv[t] : -1e38f;
            int   p2 = have ? s_rp[t] : 0x7FFFFFFF;
            float x2 = have ? s_rx[t] : 0.f;
            float y2 = have ? s_ry[t] : 0.f;
            float z2 = have ? s_rz[t] : 0.f;
#pragma unroll
            for (int o = 16; o > 0; o >>= 1) {
                float ov = __shfl_down_sync(0xffffffffu, v2, o);
                int   op = __shfl_down_sync(0xffffffffu, p2, o);
                float ox = __shfl_down_sync(0xffffffffu, x2, o);
                float oy = __shfl_down_sync(0xffffffffu, y2, o);
                float oz = __shfl_down_sync(0xffffffffu, z2, o);
                bool take = (ov > v2) || (ov == v2 && op < p2);
                if (take) { v2 = ov; p2 = op; x2 = ox; y2 = oy; z2 = oz; }
            }
            if (t == 0) { s_cidx[k] = p2; s_lx = x2; s_ly = y2; s_lz = z2; }
        }
        __syncthreads();
    }

    // tail: gather centers (all 4 channels), write scratch + output (first 256)
    {
        int p = s_cidx[t];
        float4 v = __ldg(&P[p]);
        g_centers[b * NG + t] = v;
        if (t < CTX) {
            ((float4*)out_centers)[b * CTX + t] = v;
        }
    }
}

// =====================================================================
// K2: ball query. Warp owns 4 centers; streams all points (L1/L2-hot),
// ballot+popc gives exact in-index-order candidate rank (first 512 kept).
// Candidate key packs (orderable energy bits << 32) | (0xFFFFFFFF - idx)
// so a descending u64 sort == (energy desc, index asc).
// =====================================================================
#define CPW 4
#define BQ_T 256   // 8 warps -> 32 centers per CTA; grid (16, 8)

__global__ __launch_bounds__(BQ_T, 4)
void ballquery_kernel(const float4* __restrict__ pts, const int* __restrict__ lengths) {
    const int b = blockIdx.y;
    const int w = threadIdx.x >> 5, lane = threadIdx.x & 31;
    const int cbase = blockIdx.x * 32 + w * CPW;      // center index within batch
    const int len = lengths[b];
    const float4* __restrict__ P = pts + (size_t)b * NPTS;

    float cx[CPW], cy[CPW], cz[CPW];
    int cnt[CPW];
#pragma unroll
    for (int c = 0; c < CPW; c++) {
        float4 cc = g_centers[b * NG + cbase + c];
        cx[c] = cc.x; cy[c] = cc.y; cz[c] = cc.z; cnt[c] = 0;
    }
    unsigned long long* __restrict__ buf = g_cand + (size_t)(b * NG + cbase) * UK;

    const int lim = (len + 31) & ~31;
    const unsigned lt = (1u << lane) - 1u;

    for (int p0 = 0; p0 < lim; p0 += 32) {
        int p = p0 + lane;
        float4 v = __ldg(&P[p]);
        bool inlen = (p < len);
        unsigned eb = __float_as_uint(v.w);
        unsigned ekey = (eb & 0x80000000u) ? ~eb : (eb | 0x80000000u);   // orderable float
        unsigned long long pk = ((unsigned long long)ekey << 32) | (unsigned)(0xFFFFFFFFu - (unsigned)p);

#pragma unroll
        for (int c = 0; c < CPW; c++) {
            if (cnt[c] < UK) {   // warp-uniform
                float dx = v.x - cx[c], dy = v.y - cy[c], dz = v.z - cz[c];
                float d2 = d2_exact(dx, dy, dz);
                bool pred = inlen && (d2 < R2);
                unsigned m = __ballot_sync(0xffffffffu, pred);
                int rank = cnt[c] + __popc(m & lt);
                if (pred && rank < UK) buf[(size_t)c * UK + rank] = pk;
                cnt[c] = min(UK, cnt[c] + __popc(m));
            }
        }
        if (cnt[0] >= UK && cnt[1] >= UK && cnt[2] >= UK && cnt[3] >= UK) break;
    }
    if (lane == 0) {
#pragma unroll
        for (int c = 0; c < CPW; c++) g_cand_cnt[b * NG + cbase + c] = cnt[c];
    }
}

// =====================================================================
// K3: per-group bitonic-512 descending sort of candidate keys, then emit
// groups / point_mask / group_length contribution. grid (512, 8), 256 thr.
// =====================================================================
__global__ __launch_bounds__(256, 8)
void sort_emit_kernel(const float4* __restrict__ pts,
                      float* __restrict__ out_groups /* d_out */,
                      float* __restrict__ out_pmask  /* d_out + OFF_PMASK */) {
    const int gi = blockIdx.x;       // 0..511
    const int b  = blockIdx.y;
    const int g  = b * NG + gi;
    const int t  = threadIdx.x;

    __shared__ unsigned long long s[UK];
    const int cnt = g_cand_cnt[g];
    const unsigned long long* __restrict__ src = g_cand + (size_t)g * UK;

    s[t]       = (t       < cnt) ? src[t]       : 0ull;
    s[t + 256] = (t + 256 < cnt) ? src[t + 256] : 0ull;

    // bitonic sort, descending
    for (int kk = 2; kk <= UK; kk <<= 1) {
        for (int j = kk >> 1; j > 0; j >>= 1) {
            __syncthreads();
#pragma unroll
            for (int r = 0; r < 2; r++) {
                int e = t + r * 256;
                int l = e ^ j;
                if (l > e) {
                    unsigned long long a = s[e], c = s[l];
                    bool dsc = ((e & kk) == 0);
                    bool sw = dsc ? (a < c) : (a > c);
                    if (sw) { s[e] = c; s[l] = a; }
                }
            }
        }
    }
    __syncthreads();

    const int pl = min(cnt, GS);     // point_length
    if (t == 0 && cnt >= GS) atomicAdd(&g_group_len[b], 1);

    if (gi < CTX) {
        if (t < GS * 4) {            // groups: 32 slots x 4 channels
            int slot = t >> 2, ch = t & 3;
            int ss = (slot < pl) ? slot : 0;   // fill_empty -> first index (cnt>=1 always)
            unsigned p = 0xFFFFFFFFu - (unsigned)(s[ss] & 0xFFFFFFFFull);
            const float* pp = (const float*)(pts + ((size_t)b * NPTS + p));
            out_groups[(((size_t)(b * CTX + gi)) * GS + slot) * 4 + ch] = pp[ch];
        } else if (t < GS * 4 + GS) { // point_mask
            int slot = t - GS * 4;
            out_pmask[(size_t)(b * CTX + gi) * GS + slot] = (slot < pl) ? 1.0f : 0.0f;
        }
    }
}

// =====================================================================
// K4: embedding mask
// =====================================================================
__global__ void emask_kernel(float* __restrict__ em) {
    int b = blockIdx.x, t = threadIdx.x;
    em[b * CTX + t] = (t < g_group_len[b]) ? 1.0f : 0.0f;
}

// =====================================================================
extern "C" void kernel_launch(void* const* d_in, const int* in_sizes, int n_in,
                              void* d_out, int out_size) {
    const float4* pts = (const float4*)d_in[0];   // (8,16384,4) f32
    const int*   lens = (const int*)d_in[1];      // (8,)
    float* out = (float*)d_out;

    fps_kernel<<<BB, FPS_T>>>(pts, lens, out + OFF_CENTERS);
    ballquery_kernel<<<dim3(16, BB), BQ_T>>>(pts, lens);
    sort_emit_kernel<<<dim3(NG, BB), 256>>>(pts, out + OFF_GROUPS, out + OFF_PMASK);
    emask_kernel<<<BB, CTX>>>(out + OFF_EMASK);
}

// round 2
// speedup vs baseline: 1.8936x; 1.8936x over previous
#include <cuda_runtime.h>
#include <cuda_bf16.h>

// Problem constants
#define BB 8
#define NPTS 16384
#define NG 512          // NUM_GROUPS
#define GS 32           // GROUP_SIZE
#define UK 512          // UPSCALE_K
#define CTX 256         // CONTEXT
#define R2 0.25f        // RADIUS^2

// Output layout (float32, flattened concat of the reference tuple)
#define OFF_GROUPS   0          // 8*256*32*4 = 262144
#define OFF_CENTERS  262144     // 8*256*4   = 8192
#define OFF_EMASK    270336     // 8*256     = 2048
#define OFF_PMASK    272384     // 8*256*32  = 65536

// ---------------- device scratch (no allocations allowed) ----------------
__device__ float4             g_centers[BB * NG];
__device__ unsigned long long g_cand[(size_t)BB * NG * UK];       // 16MB candidate keys
__device__ int                g_cand_cnt[BB * NG];
__device__ int                g_group_len[BB];

// exact (no fma contraction) squared distance, reduce order ((dx^2+dy^2)+dz^2)
__device__ __forceinline__ float d2_exact(float dx, float dy, float dz) {
    return __fadd_rn(__fadd_rn(__fmul_rn(dx, dx), __fmul_rn(dy, dy)), __fmul_rn(dz, dz));
}

// =====================================================================
// K1: FPS. 1 CTA/batch, 512 threads. xyz in SMEM (192KB dynamic),
// mind[32] in registers (fully unrolled -> no spills).
// =====================================================================
#define FPS_T 512
#define SLOTS 32
#define FPS_SMEM (NPTS * 12)   // float2 xy (128KB) + float z (64KB)

__global__ __launch_bounds__(FPS_T, 1)
void fps_kernel(const float4* __restrict__ pts, const int* __restrict__ lengths,
                float* __restrict__ out_centers /* d_out + OFF_CENTERS */) {
    extern __shared__ float smx[];
    float2* __restrict__ pxy = (float2*)smx;      // [NPTS]
    float*  __restrict__ pz  = smx + 2 * NPTS;    // [NPTS]
    __shared__ float s_w[16];
    __shared__ float s_gv;
    __shared__ int   s_bp;
    __shared__ int   s_cidx[NG];

    const int b = blockIdx.x, t = threadIdx.x;
    const int wid = t >> 5, lane = t & 31;
    const float4* __restrict__ P = pts + (size_t)b * NPTS;
    const int len = lengths[b];

    float mind[SLOTS];
#pragma unroll
    for (int i = 0; i < SLOTS; i++) {
        int p = i * FPS_T + t;
        float4 v = P[p];
        bool valid = (p < len);
        pxy[p] = make_float2(valid ? v.x : 1e18f, valid ? v.y : 1e18f);
        pz[p]  = valid ? v.z : 1e18f;
        mind[i] = valid ? 1e10f : -1e30f;         // invalid can never win argmax
    }
    if (t == 0) { s_bp = 0; s_cidx[0] = 0; g_group_len[b] = 0; }
    __syncthreads();

    for (int k = 1; k < NG; k++) {
        // winner coords broadcast from smem (conflict-free broadcast)
        const int wp = s_bp;
        const float2 lxy = pxy[wp];
        const float lz = pz[wp];

        // one-pass update + per-thread running max (value only)
        float fm = -1e30f;
#pragma unroll
        for (int i = 0; i < SLOTS; i++) {
            int p = i * FPS_T + t;
            float2 q = pxy[p];
            float dz = pz[p] - lz;
            float dx = q.x - lxy.x, dy = q.y - lxy.y;
            float d2 = d2_exact(dx, dy, dz);
            float m = fminf(mind[i], d2);
            mind[i] = m;
            fm = fmaxf(fm, m);
        }
        // warp max (xor: result uniform across warp)
#pragma unroll
        for (int o = 16; o > 0; o >>= 1)
            fm = fmaxf(fm, __shfl_xor_sync(0xffffffffu, fm, o));
        if (lane == 0) s_w[wid] = fm;
        __syncthreads();                           // bar1
        if (t == 0) {
            float g = s_w[0];
#pragma unroll
            for (int j = 1; j < 16; j++) g = fmaxf(g, s_w[j]);
            s_gv = g;
            s_bp = 0x7FFFFFFF;
        }
        __syncthreads();                           // bar2
        const float gv = s_gv;
        if (fm == gv) {                            // warp-uniform: losers skip
            int bp = 0x7FFFFFFF;
#pragma unroll
            for (int i = SLOTS - 1; i >= 0; i--)   // descending: last write = smallest idx
                if (mind[i] == gv) bp = i * FPS_T + t;
            if (bp != 0x7FFFFFFF) atomicMin_block(&s_bp, bp);
        }
        __syncthreads();                           // bar3: s_bp final
        if (t == 0) s_cidx[k] = s_bp;
    }
    __syncthreads();

    // tail: gather centers (all 4 channels incl. energy) from gmem
    {
        int p = s_cidx[t];
        float4 v = __ldg(&P[p]);
        g_centers[b * NG + t] = v;
        if (t < CTX) ((float4*)out_centers)[b * CTX + t] = v;
    }
}

// =====================================================================
// K2: ball query. Warp owns 4 centers; streams all points (L1/L2-hot),
// ballot+popc gives exact in-index-order candidate rank (first 512 kept).
// Key packs (orderable energy bits << 32) | (0xFFFFFFFF - idx):
// descending u64 sort == (energy desc, index asc).
// =====================================================================
#define CPW 4
#define BQ_T 256   // 8 warps -> 32 centers per CTA; grid (16, 8)

__global__ __launch_bounds__(BQ_T, 4)
void ballquery_kernel(const float4* __restrict__ pts, const int* __restrict__ lengths) {
    const int b = blockIdx.y;
    const int w = threadIdx.x >> 5, lane = threadIdx.x & 31;
    const int cbase = blockIdx.x * 32 + w * CPW;
    const int len = lengths[b];
    const float4* __restrict__ P = pts + (size_t)b * NPTS;

    float cx[CPW], cy[CPW], cz[CPW];
    int cnt[CPW];
#pragma unroll
    for (int c = 0; c < CPW; c++) {
        float4 cc = g_centers[b * NG + cbase + c];
        cx[c] = cc.x; cy[c] = cc.y; cz[c] = cc.z; cnt[c] = 0;
    }
    unsigned long long* __restrict__ buf = g_cand + (size_t)(b * NG + cbase) * UK;

    const int lim = (len + 31) & ~31;
    const unsigned lt = (1u << lane) - 1u;

    for (int p0 = 0; p0 < lim; p0 += 32) {
        int p = p0 + lane;
        float4 v = __ldg(&P[p]);
        bool inlen = (p < len);
        unsigned eb = __float_as_uint(v.w);
        unsigned ekey = (eb & 0x80000000u) ? ~eb : (eb | 0x80000000u);
        unsigned long long pk = ((unsigned long long)ekey << 32) | (unsigned)(0xFFFFFFFFu - (unsigned)p);

#pragma unroll
        for (int c = 0; c < CPW; c++) {
            if (cnt[c] < UK) {   // warp-uniform
                float dx = v.x - cx[c], dy = v.y - cy[c], dz = v.z - cz[c];
                float d2 = d2_exact(dx, dy, dz);
                bool pred = inlen && (d2 < R2);
                unsigned m = __ballot_sync(0xffffffffu, pred);
                int rank = cnt[c] + __popc(m & lt);
                if (pred && rank < UK) buf[(size_t)c * UK + rank] = pk;
                cnt[c] = min(UK, cnt[c] + __popc(m));
            }
        }
        if (cnt[0] >= UK && cnt[1] >= UK && cnt[2] >= UK && cnt[3] >= UK) break;
    }
    if (lane == 0) {
#pragma unroll
        for (int c = 0; c < CPW; c++) g_cand_cnt[b * NG + cbase + c] = cnt[c];
    }
}

// =====================================================================
// K3: per-group bitonic-512 descending sort of candidate keys, then emit
// groups / point_mask / group_length contribution. grid (512, 8), 256 thr.
// =====================================================================
__global__ __launch_bounds__(256, 8)
void sort_emit_kernel(const float4* __restrict__ pts,
                      float* __restrict__ out_groups /* d_out */,
                      float* __restrict__ out_pmask  /* d_out + OFF_PMASK */) {
    const int gi = blockIdx.x;
    const int b  = blockIdx.y;
    const int g  = b * NG + gi;
    const int t  = threadIdx.x;

    __shared__ unsigned long long s[UK];
    const int cnt = g_cand_cnt[g];
    const unsigned long long* __restrict__ src = g_cand + (size_t)g * UK;

    s[t]       = (t       < cnt) ? src[t]       : 0ull;
    s[t + 256] = (t + 256 < cnt) ? src[t + 256] : 0ull;

    for (int kk = 2; kk <= UK; kk <<= 1) {
        for (int j = kk >> 1; j > 0; j >>= 1) {
            __syncthreads();
#pragma unroll
            for (int r = 0; r < 2; r++) {
                int e = t + r * 256;
                int l = e ^ j;
                if (l > e) {
                    unsigned long long a = s[e], c = s[l];
                    bool dsc = ((e & kk) == 0);
                    bool sw = dsc ? (a < c) : (a > c);
                    if (sw) { s[e] = c; s[l] = a; }
                }
            }
        }
    }
    __syncthreads();

    const int pl = min(cnt, GS);
    if (t == 0 && cnt >= GS) atomicAdd(&g_group_len[b], 1);

    if (gi < CTX) {
        if (t < GS * 4) {
            int slot = t >> 2, ch = t & 3;
            int ss = (slot < pl) ? slot : 0;
            unsigned p = 0xFFFFFFFFu - (unsigned)(s[ss] & 0xFFFFFFFFull);
            const float* pp = (const float*)(pts + ((size_t)b * NPTS + p));
            out_groups[(((size_t)(b * CTX + gi)) * GS + slot) * 4 + ch] = pp[ch];
        } else if (t < GS * 4 + GS) {
            int slot = t - GS * 4;
            out_pmask[(size_t)(b * CTX + gi) * GS + slot] = (slot < pl) ? 1.0f : 0.0f;
        }
    }
}

// =====================================================================
// K4: embedding mask
// =====================================================================
__global__ void emask_kernel(float* __restrict__ em) {
    int b = blockIdx.x, t = threadIdx.x;
    em[b * CTX + t] = (t < g_group_len[b]) ? 1.0f : 0.0f;
}

// =====================================================================
extern "C" void kernel_launch(void* const* d_in, const int* in_sizes, int n_in,
                              void* d_out, int out_size) {
    const float4* pts = (const float4*)d_in[0];   // (8,16384,4) f32
    const int*   lens = (const int*)d_in[1];      // (8,)
    float* out = (float*)d_out;

    cudaFuncSetAttribute(fps_kernel, cudaFuncAttributeMaxDynamicSharedMemorySize, FPS_SMEM);

    fps_kernel<<<BB, FPS_T, FPS_SMEM>>>(pts, lens, out + OFF_CENTERS);
    ballquery_kernel<<<dim3(16, BB), BQ_T>>>(pts, lens);
    sort_emit_kernel<<<dim3(NG, BB), 256>>>(pts, out + OFF_GROUPS, out + OFF_PMASK);
    emask_kernel<<<BB, CTX>>>(out + OFF_EMASK);
}

// round 3
// speedup vs baseline: 2.3690x; 1.2511x over previous
#include <cuda_runtime.h>
#include <cuda_bf16.h>

// Problem constants
#define BB 8
#define NPTS 16384
#define NG 512          // NUM_GROUPS
#define GS 32           // GROUP_SIZE
#define UK 512          // UPSCALE_K
#define CTX 256         // CONTEXT
#define R2 0.25f        // RADIUS^2

// Output layout (float32, flattened concat of the reference tuple)
#define OFF_GROUPS   0          // 8*256*32*4 = 262144
#define OFF_CENTERS  262144     // 8*256*4   = 8192
#define OFF_EMASK    270336     // 8*256     = 2048
#define OFF_PMASK    272384     // 8*256*32  = 65536

// ---------------- device scratch (no allocations allowed) ----------------
__device__ float4             g_centers[BB * NG];
__device__ unsigned long long g_cand[(size_t)BB * NG * UK];       // 16MB candidate keys
__device__ int                g_cand_cnt[BB * NG];
__device__ int                g_group_len[BB];

// exact (no fma contraction) squared distance, reduce order ((dx^2+dy^2)+dz^2)
__device__ __forceinline__ float d2_exact(float dx, float dy, float dz) {
    return __fadd_rn(__fadd_rn(__fmul_rn(dx, dx), __fmul_rn(dy, dy)), __fmul_rn(dz, dz));
}

__device__ __forceinline__ unsigned smem_u32(const void* p) {
    return (unsigned)__cvta_generic_to_shared(p);
}

// =====================================================================
// K1: cluster-parallel FPS. 8 CTAs per batch (one cluster), 256 thr each.
// Shard of 2048 pts per CTA: xyz in smem, mind[8] in registers.
// Per iter: local update+argmax -> u64 key -> broadcast candidate to all
// ranks via st.shared::cluster -> ONE cluster barrier -> local 8-way reduce.
// =====================================================================
#define FC 8                     // cluster size (CTAs per batch)
#define FPS_CT 256               // threads per CTA
#define SH (NPTS / FC)           // 2048 points per shard
#define FSLOTS (SH / FPS_CT)     // 8 points per thread

__global__ void __cluster_dims__(FC, 1, 1) __launch_bounds__(FPS_CT, 1)
fps_cluster_kernel(const float4* __restrict__ pts, const int* __restrict__ lengths,
                   float* __restrict__ out_centers /* d_out + OFF_CENTERS */) {
    __shared__ float2 sxy[SH];                    // 16KB
    __shared__ float  sz[SH];                     // 8KB
    __shared__ unsigned long long s_wk[FC];       // per-warp keys (8 warps)
    __shared__ unsigned long long s_ck[2][FC];    // candidate keys (double buffered)
    __shared__ float2 s_cxy[2][FC];
    __shared__ float  s_cz[2][FC];
    __shared__ float4 s_win;                      // current winner {x,y,z,idx}
    __shared__ int    s_cidx[NG];                 // used by rank 0 only

    const int b    = blockIdx.x / FC;
    const int rank = blockIdx.x % FC;
    const int t    = threadIdx.x;
    const int wid  = t >> 5, lane = t & 31;
    const int base = rank * SH;
    const float4* __restrict__ P = pts + (size_t)b * NPTS;
    const int len = lengths[b];

    float mind[FSLOTS];
#pragma unroll
    for (int i = 0; i < FSLOTS; i++) {
        int lp = i * FPS_CT + t;
        int p  = base + lp;
        float4 v = P[p];
        bool valid = (p < len);
        sxy[lp] = make_float2(valid ? v.x : 1e18f, valid ? v.y : 1e18f);
        sz[lp]  = valid ? v.z : 1e18f;
        mind[i] = valid ? 1e10f : -1e30f;         // invalid can never win
    }
    if (t == 0) {
        float4 v0 = __ldg(&P[0]);
        s_win = make_float4(v0.x, v0.y, v0.z, __int_as_float(0));
        if (rank == 0) { s_cidx[0] = 0; g_group_len[b] = 0; }
    }
    __syncthreads();
    asm volatile("barrier.cluster.arrive.aligned;" ::: "memory");
    asm volatile("barrier.cluster.wait.aligned;"   ::: "memory");

    for (int k = 1; k < NG; k++) {
        const float4 w = s_win;
        const float lx = w.x, ly = w.y, lz = w.z;

        // (A) shard update + per-thread argmax (strict > : smallest idx wins ties)
        float bv = -1e38f; int bp = base;
#pragma unroll
        for (int i = 0; i < FSLOTS; i++) {
            int lp = i * FPS_CT + t;
            float2 q = sxy[lp];
            float dz = sz[lp] - lz;
            float d2 = d2_exact(q.x - lx, q.y - ly, dz);
            float m = fminf(mind[i], d2);
            mind[i] = m;
            if (m > bv) { bv = m; bp = base + lp; }
        }
        // order-preserving key: max(key) == (value desc, index asc)
        unsigned vb = __float_as_uint(bv);
        unsigned ek = (vb & 0x80000000u) ? ~vb : (vb | 0x80000000u);
        unsigned long long key =
            ((unsigned long long)ek << 32) | (unsigned)(0xFFFFFFFFu - (unsigned)bp);

        // (B1) warp reduce (max key)
#pragma unroll
        for (int o = 16; o > 0; o >>= 1) {
            unsigned long long ok = __shfl_down_sync(0xffffffffu, key, o);
            key = (ok > key) ? ok : key;
        }
        if (lane == 0) s_wk[wid] = key;
        __syncthreads();

        const int par = k & 1;
        // (B2) warp 0 lanes 0..7: cross-warp reduce, then lane 0 publishes
        if (t < FC) {
            unsigned long long kk = s_wk[t];
#pragma unroll
            for (int o = 4; o > 0; o >>= 1) {
                unsigned long long ok = __shfl_down_sync(0xFFu, kk, o);
                kk = (ok > kk) ? ok : kk;
            }
            if (t == 0) {
                int gbp = (int)(0xFFFFFFFFu - (unsigned)(kk & 0xFFFFFFFFull));
                int lp = gbp - base;
                float2 q = sxy[lp];
                float zz = sz[lp];
                unsigned long long xy =
                    ((unsigned long long)__float_as_uint(q.y) << 32) | __float_as_uint(q.x);
                unsigned ak  = smem_u32(&s_ck[par][rank]);
                unsigned axy = smem_u32(&s_cxy[par][rank]);
                unsigned az  = smem_u32(&s_cz[par][rank]);
#pragma unroll
                for (int r = 0; r < FC; r++) {
                    unsigned dk, dxy, dzz;
                    asm("mapa.shared::cluster.u32 %0, %1, %2;" : "=r"(dk)  : "r"(ak),  "r"(r));
                    asm("mapa.shared::cluster.u32 %0, %1, %2;" : "=r"(dxy) : "r"(axy), "r"(r));
                    asm("mapa.shared::cluster.u32 %0, %1, %2;" : "=r"(dzz) : "r"(az),  "r"(r));
                    asm volatile("st.shared::cluster.b64 [%0], %1;" :: "r"(dk),  "l"(kk) : "memory");
                    asm volatile("st.shared::cluster.b64 [%0], %1;" :: "r"(dxy), "l"(xy) : "memory");
                    asm volatile("st.shared::cluster.b32 [%0], %1;" :: "r"(dzz), "r"(__float_as_uint(zz)) : "memory");
                }
            }
        }

        // (C) one cluster barrier: publishes visible everywhere
        asm volatile("barrier.cluster.arrive.aligned;" ::: "memory");
        asm volatile("barrier.cluster.wait.aligned;"   ::: "memory");

        // (D) local 8-way reduce of candidates -> new winner
        if (t == 0) {
            unsigned long long bk = 0ull; int bs = 0;
#pragma unroll
            for (int r = 0; r < FC; r++) {
                unsigned long long kk = s_ck[par][r];
                if (kk > bk) { bk = kk; bs = r; }
            }
            int wi = (int)(0xFFFFFFFFu - (unsigned)(bk & 0xFFFFFFFFull));
            float2 wxy = s_cxy[par][bs];
            float  wz  = s_cz[par][bs];
            s_win = make_float4(wxy.x, wxy.y, wz, __int_as_float(wi));
            if (rank == 0) s_cidx[k] = wi;
        }
        __syncthreads();
    }

    // tail: rank 0 gathers centers (all 4 channels incl. energy)
    if (rank == 0) {
#pragma unroll
        for (int it = 0; it < NG / FPS_CT; it++) {
            int c = it * FPS_CT + t;
            int p = s_cidx[c];
            float4 v = __ldg(&P[p]);
            g_centers[b * NG + c] = v;
            if (c < CTX) ((float4*)out_centers)[b * CTX + c] = v;
        }
    }
}

// =====================================================================
// K2: ball query. Warp owns 4 centers; streams all points (L1/L2-hot),
// ballot+popc gives exact in-index-order candidate rank (first 512 kept).
// Key packs (orderable energy bits << 32) | (0xFFFFFFFF - idx):
// descending u64 sort == (energy desc, index asc).
// =====================================================================
#define CPW 4
#define BQ_T 256   // 8 warps -> 32 centers per CTA; grid (16, 8)

__global__ __launch_bounds__(BQ_T, 4)
void ballquery_kernel(const float4* __restrict__ pts, const int* __restrict__ lengths) {
    const int b = blockIdx.y;
    const int w = threadIdx.x >> 5, lane = threadIdx.x & 31;
    const int cbase = blockIdx.x * 32 + w * CPW;
    const int len = lengths[b];
    const float4* __restrict__ P = pts + (size_t)b * NPTS;

    float cx[CPW], cy[CPW], cz[CPW];
    int cnt[CPW];
#pragma unroll
    for (int c = 0; c < CPW; c++) {
        float4 cc = g_centers[b * NG + cbase + c];
        cx[c] = cc.x; cy[c] = cc.y; cz[c] = cc.z; cnt[c] = 0;
    }
    unsigned long long* __restrict__ buf = g_cand + (size_t)(b * NG + cbase) * UK;

    const int lim = (len + 31) & ~31;
    const unsigned lt = (1u << lane) - 1u;

    for (int p0 = 0; p0 < lim; p0 += 32) {
        int p = p0 + lane;
        float4 v = __ldg(&P[p]);
        bool inlen = (p < len);
        unsigned eb = __float_as_uint(v.w);
        unsigned ekey = (eb & 0x80000000u) ? ~eb : (eb | 0x80000000u);
        unsigned long long pk = ((unsigned long long)ekey << 32) | (unsigned)(0xFFFFFFFFu - (unsigned)p);

#pragma unroll
        for (int c = 0; c < CPW; c++) {
            if (cnt[c] < UK) {   // warp-uniform
                float dx = v.x - cx[c], dy = v.y - cy[c], dz = v.z - cz[c];
                float d2 = d2_exact(dx, dy, dz);
                bool pred = inlen && (d2 < R2);
                unsigned m = __ballot_sync(0xffffffffu, pred);
                int rank = cnt[c] + __popc(m & lt);
                if (pred && rank < UK) buf[(size_t)c * UK + rank] = pk;
                cnt[c] = min(UK, cnt[c] + __popc(m));
            }
        }
        if (cnt[0] >= UK && cnt[1] >= UK && cnt[2] >= UK && cnt[3] >= UK) break;
    }
    if (lane == 0) {
#pragma unroll
        for (int c = 0; c < CPW; c++) g_cand_cnt[b * NG + cbase + c] = cnt[c];
    }
}

// =====================================================================
// K3: per-group bitonic-512 descending sort of candidate keys, then emit
// groups / point_mask / group_length contribution. grid (512, 8), 256 thr.
// =====================================================================
__global__ __launch_bounds__(256, 8)
void sort_emit_kernel(const float4* __restrict__ pts,
                      float* __restrict__ out_groups /* d_out */,
                      float* __restrict__ out_pmask  /* d_out + OFF_PMASK */) {
    const int gi = blockIdx.x;
    const int b  = blockIdx.y;
    const int g  = b * NG + gi;
    const int t  = threadIdx.x;

    __shared__ unsigned long long s[UK];
    const int cnt = g_cand_cnt[g];
    const unsigned long long* __restrict__ src = g_cand + (size_t)g * UK;

    s[t]       = (t       < cnt) ? src[t]       : 0ull;
    s[t + 256] = (t + 256 < cnt) ? src[t + 256] : 0ull;

    for (int kk = 2; kk <= UK; kk <<= 1) {
        for (int j = kk >> 1; j > 0; j >>= 1) {
            __syncthreads();
#pragma unroll
            for (int r = 0; r < 2; r++) {
                int e = t + r * 256;
                int l = e ^ j;
                if (l > e) {
                    unsigned long long a = s[e], c = s[l];
                    bool dsc = ((e & kk) == 0);
                    bool sw = dsc ? (a < c) : (a > c);
                    if (sw) { s[e] = c; s[l] = a; }
                }
            }
        }
    }
    __syncthreads();

    const int pl = min(cnt, GS);
    if (t == 0 && cnt >= GS) atomicAdd(&g_group_len[b], 1);

    if (gi < CTX) {
        if (t < GS * 4) {
            int slot = t >> 2, ch = t & 3;
            int ss = (slot < pl) ? slot : 0;
            unsigned p = 0xFFFFFFFFu - (unsigned)(s[ss] & 0xFFFFFFFFull);
            const float* pp = (const float*)(pts + ((size_t)b * NPTS + p));
            out_groups[(((size_t)(b * CTX + gi)) * GS + slot) * 4 + ch] = pp[ch];
        } else if (t < GS * 4 + GS) {
            int slot = t - GS * 4;
            out_pmask[(size_t)(b * CTX + gi) * GS + slot] = (slot < pl) ? 1.0f : 0.0f;
        }
    }
}

// =====================================================================
// K4: embedding mask
// =====================================================================
__global__ void emask_kernel(float* __restrict__ em) {
    int b = blockIdx.x, t = threadIdx.x;
    em[b * CTX + t] = (t < g_group_len[b]) ? 1.0f : 0.0f;
}

// =====================================================================
extern "C" void kernel_launch(void* const* d_in, const int* in_sizes, int n_in,
                              void* d_out, int out_size) {
    const float4* pts = (const float4*)d_in[0];   // (8,16384,4) f32
    const int*   lens = (const int*)d_in[1];      // (8,)
    float* out = (float*)d_out;

    fps_cluster_kernel<<<BB * FC, FPS_CT>>>(pts, lens, out + OFF_CENTERS);
    ballquery_kernel<<<dim3(16, BB), BQ_T>>>(pts, lens);
    sort_emit_kernel<<<dim3(NG, BB), 256>>>(pts, out + OFF_GROUPS, out + OFF_PMASK);
    emask_kernel<<<BB, CTX>>>(out + OFF_EMASK);
}

// round 4
// speedup vs baseline: 2.3977x; 1.0121x over previous
#include <cuda_runtime.h>
#include <cuda_bf16.h>

// Problem constants
#define BB 8
#define NPTS 16384
#define NG 512          // NUM_GROUPS
#define GS 32           // GROUP_SIZE
#define UK 512          // UPSCALE_K
#define CTX 256         // CONTEXT
#define R2 0.25f        // RADIUS^2

// Output layout (float32, flattened concat of the reference tuple)
#define OFF_GROUPS   0          // 8*256*32*4 = 262144
#define OFF_CENTERS  262144     // 8*256*4   = 8192
#define OFF_EMASK    270336     // 8*256     = 2048
#define OFF_PMASK    272384     // 8*256*32  = 65536

// ---------------- device scratch (no allocations allowed) ----------------
__device__ float4             g_centers[BB * NG];
__device__ unsigned long long g_cand[(size_t)BB * NG * UK];       // 16MB candidate keys
__device__ int                g_cand_cnt[BB * NG];
__device__ int                g_group_len[BB];

// exact (no fma contraction) squared distance, reduce order ((dx^2+dy^2)+dz^2)
__device__ __forceinline__ float d2_exact(float dx, float dy, float dz) {
    return __fadd_rn(__fadd_rn(__fmul_rn(dx, dx), __fmul_rn(dy, dy)), __fmul_rn(dz, dz));
}

__device__ __forceinline__ unsigned smem_u32(const void* p) {
    return (unsigned)__cvta_generic_to_shared(p);
}

__device__ __forceinline__ unsigned redux_max_u32(unsigned v) {
    unsigned r;
    asm("redux.sync.max.u32 %0, %1, 0xffffffff;" : "=r"(r) : "r"(v));
    return r;
}
__device__ __forceinline__ unsigned redux_min_u32(unsigned v) {
    unsigned r;
    asm("redux.sync.min.u32 %0, %1, 0xffffffff;" : "=r"(r) : "r"(v));
    return r;
}

// =====================================================================
// K1: cluster-parallel FPS. 8 CTAs per batch, 512 threads, 4 pts/thread.
// Per iter: shard update + redux argmax -> CTA candidate -> 8 threads each
// publish (st.shared::cluster x3 + mbarrier.arrive.release.cluster) to one
// peer -> t0 waits 8 arrivals on local mbarrier -> 8-way reduce -> next.
// Double-buffered candidate slots by iteration parity.
// =====================================================================
#define FC 8                     // cluster size (CTAs per batch)
#define FPS_CT 512               // threads per CTA
#define SH (NPTS / FC)           // 2048 points per shard
#define FSLOTS (SH / FPS_CT)     // 4 points per thread

__global__ void __cluster_dims__(FC, 1, 1) __launch_bounds__(FPS_CT, 1)
fps_cluster_kernel(const float4* __restrict__ pts, const int* __restrict__ lengths,
                   float* __restrict__ out_centers /* d_out + OFF_CENTERS */) {
    __shared__ float2 sxy[SH];                    // 16KB
    __shared__ float  sz[SH];                     // 8KB
    __shared__ unsigned long long s_wk[16];       // per-warp keys
    __shared__ unsigned long long s_ck[2][FC];    // candidate keys (double buffered)
    __shared__ float2 s_cxy[2][FC];
    __shared__ float  s_cz[2][FC];
    __shared__ unsigned long long s_mbar;         // arrival barrier (count=8/phase)
    __shared__ float4 s_win;                      // current winner {x,y,z,idx}
    __shared__ int    s_cidx[NG];                 // used by rank 0 only

    const int b    = blockIdx.x / FC;
    const int rank = blockIdx.x % FC;
    const int t    = threadIdx.x;
    const int wid  = t >> 5, lane = t & 31;
    const int base = rank * SH;
    const float4* __restrict__ P = pts + (size_t)b * NPTS;
    const int len = lengths[b];

    float mind[FSLOTS];
#pragma unroll
    for (int i = 0; i < FSLOTS; i++) {
        int lp = i * FPS_CT + t;
        int p  = base + lp;
        float4 v = P[p];
        bool valid = (p < len);
        sxy[lp] = make_float2(valid ? v.x : 1e18f, valid ? v.y : 1e18f);
        sz[lp]  = valid ? v.z : 1e18f;
        mind[i] = valid ? 1e10f : -1e30f;         // invalid can never win
    }
    if (t == 0) {
        float4 v0 = __ldg(&P[0]);
        s_win = make_float4(v0.x, v0.y, v0.z, __int_as_float(0));
        asm volatile("mbarrier.init.shared.b64 [%0], %1;" :: "r"(smem_u32(&s_mbar)), "r"(FC) : "memory");
        if (rank == 0) { s_cidx[0] = 0; g_group_len[b] = 0; }
    }
    __syncthreads();
    // cluster-wide: all mbarriers initialized before any remote arrive
    asm volatile("barrier.cluster.arrive.aligned;" ::: "memory");
    asm volatile("barrier.cluster.wait.aligned;"   ::: "memory");

    for (int k = 1; k < NG; k++) {
        const float4 w = s_win;
        const float lx = w.x, ly = w.y, lz = w.z;

        // (A) shard update + per-thread argmax (strict > : smallest idx wins)
        float bv = -1e38f; int bp = base;
#pragma unroll
        for (int i = 0; i < FSLOTS; i++) {
            int lp = i * FPS_CT + t;
            float2 q = sxy[lp];
            float dz = sz[lp] - lz;
            float d2 = d2_exact(q.x - lx, q.y - ly, dz);
            float m = fminf(mind[i], d2);
            mind[i] = m;
            if (m > bv) { bv = m; bp = base + lp; }
        }
        // warp argmax via redux: max orderable value, then min index of matches
        unsigned vb = __float_as_uint(bv);
        unsigned ek = (vb & 0x80000000u) ? ~vb : (vb | 0x80000000u);
        unsigned wm = redux_max_u32(ek);
        unsigned wi = redux_min_u32((ek == wm) ? (unsigned)bp : 0xFFFFFFFFu);
        if (lane == 0)
            s_wk[wid] = ((unsigned long long)wm << 32) | (0xFFFFFFFFu - wi);
        __syncthreads();

        const int par = k & 1;
        // (B) 8 threads: serial reduce of 16 warp keys, each publishes to peer t
        if (t < FC) {
            unsigned long long best = s_wk[0];
#pragma unroll
            for (int j = 1; j < 16; j++) {
                unsigned long long kk = s_wk[j];
                if (kk > best) best = kk;
            }
            int gbp = (int)(0xFFFFFFFFu - (unsigned)(best & 0xFFFFFFFFull));
            int lp = gbp - base;                   // winner is in this shard
            float2 q = sxy[lp];
            float zz = sz[lp];
            unsigned long long xy =
                ((unsigned long long)__float_as_uint(q.y) << 32) | __float_as_uint(q.x);
            unsigned ak  = smem_u32(&s_ck[par][rank]);
            unsigned axy = smem_u32(&s_cxy[par][rank]);
            unsigned az  = smem_u32(&s_cz[par][rank]);
            unsigned am  = smem_u32(&s_mbar);
            unsigned dk, dxy, dzz, dm;
            asm("mapa.shared::cluster.u32 %0, %1, %2;" : "=r"(dk)  : "r"(ak),  "r"(t));
            asm("mapa.shared::cluster.u32 %0, %1, %2;" : "=r"(dxy) : "r"(axy), "r"(t));
            asm("mapa.shared::cluster.u32 %0, %1, %2;" : "=r"(dzz) : "r"(az),  "r"(t));
            asm("mapa.shared::cluster.u32 %0, %1, %2;" : "=r"(dm)  : "r"(am),  "r"(t));
            asm volatile("st.shared::cluster.b64 [%0], %1;" :: "r"(dk),  "l"(best) : "memory");
            asm volatile("st.shared::cluster.b64 [%0], %1;" :: "r"(dxy), "l"(xy)   : "memory");
            asm volatile("st.shared::cluster.b32 [%0], %1;" :: "r"(dzz), "r"(__float_as_uint(zz)) : "memory");
            asm volatile("mbarrier.arrive.release.cluster.shared::cluster.b64 _, [%0];"
                         :: "r"(dm) : "memory");
        }

        // (C) t0: wait for 8 arrivals (parity flips once per iteration)
        if (t == 0) {
            unsigned parity = (k - 1) & 1;
            unsigned mb = smem_u32(&s_mbar);
            asm volatile(
                "{\n\t.reg .pred P1;\n\t"
                "WAIT_%=:\n\t"
                "mbarrier.try_wait.parity.acquire.cluster.shared::cta.b64 P1, [%0], %1, 0x989680;\n\t"
                "@P1 bra.uni DONE_%=;\n\t"
                "bra.uni WAIT_%=;\n\t"
                "DONE_%=:\n\t}"
                :: "r"(mb), "r"(parity) : "memory");
            // (D) 8-way reduce of candidates -> new winner
            unsigned long long bk = 0ull; int bs = 0;
#pragma unroll
            for (int r = 0; r < FC; r++) {
                unsigned long long kk = s_ck[par][r];
                if (kk > bk) { bk = kk; bs = r; }
            }
            int wpt = (int)(0xFFFFFFFFu - (unsigned)(bk & 0xFFFFFFFFull));
            float2 wxy = s_cxy[par][bs];
            float  wz  = s_cz[par][bs];
            s_win = make_float4(wxy.x, wxy.y, wz, __int_as_float(wpt));
            if (rank == 0) s_cidx[k] = wpt;
        }
        __syncthreads();
    }

    // safety: no CTA exits while peers may still address its smem
    asm volatile("barrier.cluster.arrive.aligned;" ::: "memory");
    asm volatile("barrier.cluster.wait.aligned;"   ::: "memory");

    // tail: rank 0 gathers centers (all 4 channels incl. energy)
    if (rank == 0) {
        int c = t;                                 // 512 threads, 512 centers
        int p = s_cidx[c];
        float4 v = __ldg(&P[p]);
        g_centers[b * NG + c] = v;
        if (c < CTX) ((float4*)out_centers)[b * CTX + c] = v;
    }
}

// =====================================================================
// K2: ball query. Warp owns 4 centers; streams all points (L1/L2-hot),
// ballot+popc gives exact in-index-order candidate rank (first 512 kept).
// Key packs (orderable energy bits << 32) | (0xFFFFFFFF - idx):
// descending u64 sort == (energy desc, index asc).
// =====================================================================
#define CPW 4
#define BQ_T 256   // 8 warps -> 32 centers per CTA; grid (16, 8)

__global__ __launch_bounds__(BQ_T, 4)
void ballquery_kernel(const float4* __restrict__ pts, const int* __restrict__ lengths) {
    const int b = blockIdx.y;
    const int w = threadIdx.x >> 5, lane = threadIdx.x & 31;
    const int cbase = blockIdx.x * 32 + w * CPW;
    const int len = lengths[b];
    const float4* __restrict__ P = pts + (size_t)b * NPTS;

    float cx[CPW], cy[CPW], cz[CPW];
    int cnt[CPW];
#pragma unroll
    for (int c = 0; c < CPW; c++) {
        float4 cc = g_centers[b * NG + cbase + c];
        cx[c] = cc.x; cy[c] = cc.y; cz[c] = cc.z; cnt[c] = 0;
    }
    unsigned long long* __restrict__ buf = g_cand + (size_t)(b * NG + cbase) * UK;

    const int lim = (len + 31) & ~31;
    const unsigned lt = (1u << lane) - 1u;

    for (int p0 = 0; p0 < lim; p0 += 32) {
        int p = p0 + lane;
        float4 v = __ldg(&P[p]);
        bool inlen = (p < len);
        unsigned eb = __float_as_uint(v.w);
        unsigned ekey = (eb & 0x80000000u) ? ~eb : (eb | 0x80000000u);
        unsigned long long pk = ((unsigned long long)ekey << 32) | (unsigned)(0xFFFFFFFFu - (unsigned)p);

#pragma unroll
        for (int c = 0; c < CPW; c++) {
            if (cnt[c] < UK) {   // warp-uniform
                float dx = v.x - cx[c], dy = v.y - cy[c], dz = v.z - cz[c];
                float d2 = d2_exact(dx, dy, dz);
                bool pred = inlen && (d2 < R2);
                unsigned m = __ballot_sync(0xffffffffu, pred);
                int rnk = cnt[c] + __popc(m & lt);
                if (pred && rnk < UK) buf[(size_t)c * UK + rnk] = pk;
                cnt[c] = min(UK, cnt[c] + __popc(m));
            }
        }
        if (cnt[0] >= UK && cnt[1] >= UK && cnt[2] >= UK && cnt[3] >= UK) break;
    }
    if (lane == 0) {
#pragma unroll
        for (int c = 0; c < CPW; c++) g_cand_cnt[b * NG + cbase + c] = cnt[c];
    }
}

// =====================================================================
// K3: per-group adaptive bitonic (M = next pow2 >= cnt, min 32) descending
// sort of candidate keys, then emit. grid (512, 8), 256 threads.
// =====================================================================
__global__ __launch_bounds__(256, 8)
void sort_emit_kernel(const float4* __restrict__ pts,
                      float* __restrict__ out_groups /* d_out */,
                      float* __restrict__ out_pmask  /* d_out + OFF_PMASK */) {
    const int gi = blockIdx.x;
    const int b  = blockIdx.y;
    const int g  = b * NG + gi;
    const int t  = threadIdx.x;

    __shared__ unsigned long long s[UK];
    const int cnt = g_cand_cnt[g];
    const unsigned long long* __restrict__ src = g_cand + (size_t)g * UK;

    int M = GS;
    while (M < cnt) M <<= 1;                       // 32..512, CTA-uniform

    for (int i = t; i < M; i += 256)
        s[i] = (i < cnt) ? src[i] : 0ull;

    for (int kk = 2; kk <= M; kk <<= 1) {
        for (int j = kk >> 1; j > 0; j >>= 1) {
            __syncthreads();
            for (int e = t; e < M; e += 256) {
                int l = e ^ j;
                if (l > e) {
                    unsigned long long a = s[e], c = s[l];
                    bool dsc = ((e & kk) == 0);
                    bool sw = dsc ? (a < c) : (a > c);
                    if (sw) { s[e] = c; s[l] = a; }
                }
            }
        }
    }
    __syncthreads();

    const int pl = min(cnt, GS);
    if (t == 0 && cnt >= GS) atomicAdd(&g_group_len[b], 1);

    if (gi < CTX) {
        if (t < GS * 4) {
            int slot = t >> 2, ch = t & 3;
            int ss = (slot < pl) ? slot : 0;
            unsigned p = 0xFFFFFFFFu - (unsigned)(s[ss] & 0xFFFFFFFFull);
            const float* pp = (const float*)(pts + ((size_t)b * NPTS + p));
            out_groups[(((size_t)(b * CTX + gi)) * GS + slot) * 4 + ch] = pp[ch];
        } else if (t < GS * 4 + GS) {
            int slot = t - GS * 4;
            out_pmask[(size_t)(b * CTX + gi) * GS + slot] = (slot < pl) ? 1.0f : 0.0f;
        }
    }
}

// =====================================================================
// K4: embedding mask
// =====================================================================
__global__ void emask_kernel(float* __restrict__ em) {
    int b = blockIdx.x, t = threadIdx.x;
    em[b * CTX + t] = (t < g_group_len[b]) ? 1.0f : 0.0f;
}

// =====================================================================
extern "C" void kernel_launch(void* const* d_in, const int* in_sizes, int n_in,
                              void* d_out, int out_size) {
    const float4* pts = (const float4*)d_in[0];   // (8,16384,4) f32
    const int*   lens = (const int*)d_in[1];      // (8,)
    float* out = (float*)d_out;

    fps_cluster_kernel<<<BB * FC, FPS_CT>>>(pts, lens, out + OFF_CENTERS);
    ballquery_kernel<<<dim3(16, BB), BQ_T>>>(pts, lens);
    sort_emit_kernel<<<dim3(NG, BB), 256>>>(pts, out + OFF_GROUPS, out + OFF_PMASK);
    emask_kernel<<<BB, CTX>>>(out + OFF_EMASK);
}